// round 9
// baseline (speedup 1.0000x reference)
#include <cuda_runtime.h>
#include <math.h>
#include <stdint.h>

// ---------------- problem constants ----------------
#define BB      4
#define SEQ     1024
#define LSEQ    1024
#define DIM     1024
#define NH      16
#define HDIM    64
#define HIDDEN  4096
#define ROWS    (BB*SEQ)     // 4096

// ---------------- device scratch (no allocations allowed) ----------------
__device__ float g_x    [ROWS*DIM];
__device__ float g_qkv  [ROWS*3*DIM];
__device__ float g_attn [ROWS*DIM];
__device__ float g_tok2 [ROWS*DIM];
__device__ float g_query[ROWS*DIM];
__device__ float g_src  [ROWS*DIM];
__device__ float g_cq   [ROWS*DIM];
__device__ float g_ck   [ROWS*DIM];
__device__ float g_cv   [ROWS*DIM];
__device__ float g_att2 [ROWS*DIM];
__device__ float g_upd  [ROWS*DIM];
__device__ float g_gatep[ROWS*DIM];
__device__ float g_tok3 [ROWS*DIM];
__device__ float g_h    [ROWS*DIM];
__device__ float g_gu   [ROWS*2*HIDDEN];
__device__ float g_v2   [ROWS*HIDDEN];
__device__ float g_film [BB*2*DIM];
__device__ float g_validS[BB*SEQ];
__device__ float g_validL[BB*LSEQ];
__device__ float g_rowvalid[BB];
__device__ int   g_mask_mode;   // 0=uint8, 1=int32, 2=float32

// ---------------- mask dtype detection ----------------
// Inspect only first nbytes (= element count) bytes: safe lower bound for all dtypes.
__global__ void detect_mask_kernel(const unsigned char* p, int nbytes) {
    __shared__ int f_gt1, f_off;
    if (threadIdx.x == 0) { f_gt1 = 0; f_off = 0; }
    __syncthreads();
    for (int i = threadIdx.x; i < nbytes; i += blockDim.x) {
        unsigned char v = p[i];
        if (v > 1) atomicOr(&f_gt1, 1);
        else if (v == 1 && (i & 3)) atomicOr(&f_off, 1);
    }
    __syncthreads();
    if (threadIdx.x == 0) {
        g_mask_mode = f_gt1 ? 2 : (f_off ? 0 : 1);
    }
}

__device__ __forceinline__ int read_mask(const void* p, int idx, int mode) {
    if (mode == 0) return ((const unsigned char*)p)[idx] != 0;
    if (mode == 1) return ((const int*)p)[idx] != 0;
    return ((const float*)p)[idx] != 0.0f;
}

// valid[b*n+i] = ~safe_key_padding_mask(mask)[b,i]; rowvalid[b]=any(~mask[b]) (original mask)
__global__ void build_valid_kernel(const void* mask, int n, float* valid, float* rowvalid) {
    __shared__ int red[256];
    int b = blockIdx.x;
    int mode = g_mask_mode;
    int cnt = 0;
    for (int i = threadIdx.x; i < n; i += 256)
        cnt += read_mask(mask, b * n + i, mode);
    red[threadIdx.x] = cnt;
    __syncthreads();
    for (int s = 128; s > 0; s >>= 1) {
        if (threadIdx.x < s) red[threadIdx.x] += red[threadIdx.x + s];
        __syncthreads();
    }
    int allpad = (red[0] == n);
    for (int i = threadIdx.x; i < n; i += 256) {
        int m = read_mask(mask, b * n + i, mode);
        valid[b * n + i] = allpad ? 1.0f : (m ? 0.0f : 1.0f);
    }
    if (rowvalid && threadIdx.x == 0)
        rowvalid[b] = allpad ? 0.0f : 1.0f;
}

// ---------------- FiLM projection: out[b,j]=mod[b]·film_w[j]+film_b[j], j<2048 ----------------
__global__ void film_kernel(const float* __restrict__ mod, const float* __restrict__ w,
                            const float* __restrict__ bias, float* __restrict__ out) {
    int j = blockIdx.x * blockDim.x + threadIdx.x;
    int b = blockIdx.y;
    if (j >= 2 * DIM) return;
    const float* wr = w + (size_t)j * DIM;
    const float* mr = mod + (size_t)b * DIM;
    float s = bias[j];
    for (int k = 0; k < DIM; k++) s += mr[k] * wr[k];
    out[b * 2 * DIM + j] = s;
}

// ---------------- RMSNorm (+ optional FiLM) ----------------
__global__ void norm_film_kernel(const float* __restrict__ in, const float* __restrict__ w,
                                 const float* __restrict__ film, float* __restrict__ out) {
    __shared__ float red[256];
    int row = blockIdx.x;                 // 0..ROWS-1
    int b = row >> 10;                    // row / SEQ
    const float* x = in + (size_t)row * DIM;
    float ss = 0.0f;
    for (int d = threadIdx.x; d < DIM; d += 256) { float v = x[d]; ss += v * v; }
    red[threadIdx.x] = ss;
    __syncthreads();
    for (int s = 128; s > 0; s >>= 1) {
        if (threadIdx.x < s) red[threadIdx.x] += red[threadIdx.x + s];
        __syncthreads();
    }
    float r = rsqrtf(red[0] * (1.0f / DIM) + 1e-6f);
    for (int d = threadIdx.x; d < DIM; d += 256) {
        float v = x[d] * r * w[d];
        if (film) {
            float sc = 1.0f + 0.1f * tanhf(film[b * 2 * DIM + d]);
            v = v * sc + film[b * 2 * DIM + DIM + d];
        }
        out[(size_t)row * DIM + d] = v;
    }
}

// ---------------- SGEMM: C[M,N] = A[M,K] @ W[N,K]^T (+bias +res +accum) ----------------
// 64x64 tile, BK=16, 256 threads, 4x4 per thread.
__global__ void sgemm64(const float* __restrict__ A, int lda,
                        const float* __restrict__ W, int ldw,
                        const float* __restrict__ bias,
                        const float* __restrict__ res,
                        float* __restrict__ C, int ldc,
                        int K, int accum) {
    __shared__ float As[16][64];
    __shared__ float Ws[16][64];
    int row0 = blockIdx.y * 64;
    int col0 = blockIdx.x * 64;
    int tid = threadIdx.x;
    int tr = tid >> 4;          // 0..15
    int tc = tid & 15;          // 0..15
    int ar = tid >> 2;          // 0..63
    int ac = (tid & 3) * 4;     // 0,4,8,12

    float acc[4][4];
#pragma unroll
    for (int i = 0; i < 4; i++)
#pragma unroll
        for (int j = 0; j < 4; j++) acc[i][j] = 0.0f;

    for (int k0 = 0; k0 < K; k0 += 16) {
        float4 av = *reinterpret_cast<const float4*>(A + (size_t)(row0 + ar) * lda + k0 + ac);
        float4 wv = *reinterpret_cast<const float4*>(W + (size_t)(col0 + ar) * ldw + k0 + ac);
        As[ac + 0][ar] = av.x; As[ac + 1][ar] = av.y; As[ac + 2][ar] = av.z; As[ac + 3][ar] = av.w;
        Ws[ac + 0][ar] = wv.x; Ws[ac + 1][ar] = wv.y; Ws[ac + 2][ar] = wv.z; Ws[ac + 3][ar] = wv.w;
        __syncthreads();
#pragma unroll
        for (int kk = 0; kk < 16; kk++) {
            float4 a4 = *reinterpret_cast<const float4*>(&As[kk][tr * 4]);
            float4 b4 = *reinterpret_cast<const float4*>(&Ws[kk][tc * 4]);
            float a[4] = {a4.x, a4.y, a4.z, a4.w};
            float b[4] = {b4.x, b4.y, b4.z, b4.w};
#pragma unroll
            for (int i = 0; i < 4; i++)
#pragma unroll
                for (int j = 0; j < 4; j++) acc[i][j] += a[i] * b[j];
        }
        __syncthreads();
    }

#pragma unroll
    for (int i = 0; i < 4; i++) {
        int r = row0 + tr * 4 + i;
#pragma unroll
        for (int j = 0; j < 4; j++) {
            int c = col0 + tc * 4 + j;
            float v = acc[i][j];
            if (bias) v += bias[c];
            if (res) v += res[(size_t)r * ldc + c];
            if (accum) v += C[(size_t)r * ldc + c];
            C[(size_t)r * ldc + c] = v;
        }
    }
}

// ---------------- RoPE (in-place on q,k halves of g_qkv) ----------------
__global__ void rope_kernel(float* qkv) {
    int idx = blockIdx.x * blockDim.x + threadIdx.x;
    int total = BB * SEQ * NH * (HDIM / 2);
    if (idx >= total) return;
    int i = idx & 31;
    int h = (idx >> 5) & 15;
    int s = (idx >> 9) & 1023;
    int b = idx >> 19;
    float freq = expf((float)(2 * i) * (-0.14391156831212787f)); // -ln(10000)/64
    float ang = (float)s * freq;
    float sn, cs;
    sincosf(ang, &sn, &cs);
    size_t base = ((size_t)(b * SEQ + s)) * (3 * DIM) + h * HDIM + 2 * i;
    // q
    float e = qkv[base], o = qkv[base + 1];
    qkv[base] = e * cs - o * sn;
    qkv[base + 1] = e * sn + o * cs;
    // k
    size_t kb = base + DIM;
    e = qkv[kb]; o = qkv[kb + 1];
    qkv[kb] = e * cs - o * sn;
    qkv[kb + 1] = e * sn + o * cs;
}

// ---------------- attention: one block per (b,h,qi) ----------------
__global__ void attn_kernel(const float* __restrict__ Q, int qs,
                            const float* __restrict__ Kp, int ks,
                            const float* __restrict__ V, int vs,
                            const float* __restrict__ valid,
                            float* __restrict__ out,
                            int Sq, int Skv) {
    __shared__ float sc[1024];
    __shared__ float qv[HDIM];
    __shared__ float red[128];
    int qi = blockIdx.x;
    int bh = blockIdx.y;
    int b = bh / NH, h = bh % NH;
    int tid = threadIdx.x;

    const float* qrow = Q + ((size_t)(b * Sq + qi)) * qs + h * HDIM;
    if (tid < HDIM) qv[tid] = qrow[tid];
    __syncthreads();

    const float* kbase = Kp + ((size_t)b * Skv) * ks + h * HDIM;
    for (int t = tid; t < Skv; t += 128) {
        const float* kr = kbase + (size_t)t * ks;
        float s = 0.0f;
#pragma unroll
        for (int d = 0; d < HDIM; d += 4) {
            float4 kv4 = *reinterpret_cast<const float4*>(kr + d);
            s += qv[d] * kv4.x + qv[d + 1] * kv4.y + qv[d + 2] * kv4.z + qv[d + 3] * kv4.w;
        }
        s *= 0.125f;  // 1/sqrt(64)
        if (valid[b * Skv + t] == 0.0f) s = -1e30f;
        sc[t] = s;
    }
    __syncthreads();

    // max
    float m = -1e30f;
    for (int t = tid; t < Skv; t += 128) m = fmaxf(m, sc[t]);
    red[tid] = m;
    __syncthreads();
    for (int s = 64; s > 0; s >>= 1) {
        if (tid < s) red[tid] = fmaxf(red[tid], red[tid + s]);
        __syncthreads();
    }
    m = red[0];
    __syncthreads();

    // exp + sum
    float su = 0.0f;
    for (int t = tid; t < Skv; t += 128) {
        float e = expf(sc[t] - m);
        sc[t] = e;
        su += e;
    }
    red[tid] = su;
    __syncthreads();
    for (int s = 64; s > 0; s >>= 1) {
        if (tid < s) red[tid] += red[tid + s];
        __syncthreads();
    }
    float inv = 1.0f / red[0];
    __syncthreads();

    // AV
    int d = tid & 63;
    int half = tid >> 6;
    const float* vbase = V + ((size_t)b * Skv) * vs + h * HDIM + d;
    float accv = 0.0f;
    int t0 = half * (Skv / 2), t1 = t0 + (Skv / 2);
#pragma unroll 4
    for (int t = t0; t < t1; t++) accv += sc[t] * vbase[(size_t)t * vs];
    red[tid] = accv;
    __syncthreads();
    if (tid < 64) {
        float r = (red[tid] + red[tid + 64]) * inv;
        out[((size_t)(b * Sq + qi)) * DIM + h * HDIM + d] = r;
    }
}

// ---------------- elementwise ----------------
__global__ void scale_upd_kernel(float* upd) {
    int i = blockIdx.x * blockDim.x + threadIdx.x;
    if (i >= ROWS * DIM) return;
    upd[i] *= g_rowvalid[i >> 20];   // SEQ*DIM = 2^20 elements per batch
}

__global__ void gate_combine_kernel(const float* __restrict__ tok2, const float* __restrict__ gatep,
                                    const float* __restrict__ upd, float* __restrict__ tok3) {
    int i = blockIdx.x * blockDim.x + threadIdx.x;
    if (i >= ROWS * DIM) return;
    float g = 1.0f / (1.0f + expf(-gatep[i]));
    tok3[i] = tok2[i] + g * upd[i];
}

__global__ void silu_mul_kernel(const float* __restrict__ gu, float* __restrict__ v2) {
    int i = blockIdx.x * blockDim.x + threadIdx.x;
    if (i >= ROWS * HIDDEN) return;
    int m = i >> 12;          // row
    int j = i & 4095;         // col within HIDDEN
    float g = gu[(size_t)m * 2 * HIDDEN + j];
    float val = gu[(size_t)m * 2 * HIDDEN + HIDDEN + j];
    float sg = g / (1.0f + expf(-g));
    v2[i] = sg * val;
}

// ---------------- host launch ----------------
static float* symf(const void* devsym) {
    void* p = nullptr;
    cudaGetSymbolAddress(&p, devsym);
    return (float*)p;
}

extern "C" void kernel_launch(void* const* d_in, const int* in_sizes, int n_in,
                              void* d_out, int out_size) {
    const float* tokens     = (const float*)d_in[0];
    const float* seq_tokens = (const float*)d_in[1];
    const float* modulation = (const float*)d_in[2];
    const float* attn_norm_w= (const float*)d_in[3];
    const float* qkv_w      = (const float*)d_in[4];
    const float* qkv_b      = (const float*)d_in[5];
    const float* out_w      = (const float*)d_in[6];
    const float* out_b      = (const float*)d_in[7];
    const float* film_w     = (const float*)d_in[8];
    const float* film_b     = (const float*)d_in[9];
    const float* sq_norm_w  = (const float*)d_in[10];
    const float* s_norm_w   = (const float*)d_in[11];
    const float* mha_in_w   = (const float*)d_in[12];
    const float* mha_in_b   = (const float*)d_in[13];
    const float* mha_out_w  = (const float*)d_in[14];
    const float* mha_out_b  = (const float*)d_in[15];
    const float* gate_w     = (const float*)d_in[16];
    const float* gate_b     = (const float*)d_in[17];
    const float* ffn_norm_w = (const float*)d_in[18];
    const float* gu_w       = (const float*)d_in[19];
    const float* gu_b       = (const float*)d_in[20];
    const float* down_w     = (const float*)d_in[21];
    const float* down_b     = (const float*)d_in[22];
    const void*  padding_mask = d_in[23];
    const void*  seq_mask     = d_in[24];
    float* out = (float*)d_out;

    float* x     = symf(g_x);
    float* qkv   = symf(g_qkv);
    float* attn  = symf(g_attn);
    float* tok2  = symf(g_tok2);
    float* query = symf(g_query);
    float* src   = symf(g_src);
    float* cq    = symf(g_cq);
    float* ck    = symf(g_ck);
    float* cv    = symf(g_cv);
    float* att2  = symf(g_att2);
    float* upd   = symf(g_upd);
    float* gatep = symf(g_gatep);
    float* tok3  = symf(g_tok3);
    float* hbuf  = symf(g_h);
    float* gu    = symf(g_gu);
    float* v2    = symf(g_v2);
    float* film  = symf(g_film);
    float* validS= symf(g_validS);
    float* validL= symf(g_validL);
    float* rowv  = symf(g_rowvalid);

    // 1. mask dtype detection + valid arrays
    detect_mask_kernel<<<1, 256>>>((const unsigned char*)padding_mask, BB * SEQ);
    build_valid_kernel<<<BB, 256>>>(padding_mask, SEQ, validS, nullptr);
    build_valid_kernel<<<BB, 256>>>(seq_mask, LSEQ, validL, rowv);

    // 2. FiLM projection
    {
        dim3 grid((2 * DIM + 127) / 128, BB);
        film_kernel<<<grid, 128>>>(modulation, film_w, film_b, film);
    }

    // 3. rmsnorm + film -> x
    norm_film_kernel<<<ROWS, 256>>>(tokens, attn_norm_w, film, x);

    // 4. qkv = x @ qkv_w^T + qkv_b
    sgemm64<<<dim3(3 * DIM / 64, ROWS / 64), 256>>>(x, DIM, qkv_w, DIM, qkv_b, nullptr, qkv, 3 * DIM, DIM, 0);

    // 5. rope in place
    {
        int total = BB * SEQ * NH * (HDIM / 2);
        rope_kernel<<<(total + 255) / 256, 256>>>(qkv);
    }

    // 6. self attention -> attn (merged heads)
    attn_kernel<<<dim3(SEQ, BB * NH), 128>>>(qkv, 3 * DIM, qkv + DIM, 3 * DIM, qkv + 2 * DIM, 3 * DIM,
                                             validS, attn, SEQ, SEQ);

    // 7. tok2 = tokens + attn @ out_w^T + out_b
    sgemm64<<<dim3(DIM / 64, ROWS / 64), 256>>>(attn, DIM, out_w, DIM, out_b, tokens, tok2, DIM, DIM, 0);

    // 8. norms
    norm_film_kernel<<<ROWS, 256>>>(tok2, sq_norm_w, nullptr, query);
    norm_film_kernel<<<ROWS, 256>>>(seq_tokens, s_norm_w, nullptr, src);

    // 9. cross q/k/v
    sgemm64<<<dim3(DIM / 64, ROWS / 64), 256>>>(query, DIM, mha_in_w, DIM, mha_in_b, nullptr, cq, DIM, DIM, 0);
    sgemm64<<<dim3(DIM / 64, ROWS / 64), 256>>>(src, DIM, mha_in_w + (size_t)DIM * DIM, DIM, mha_in_b + DIM, nullptr, ck, DIM, DIM, 0);
    sgemm64<<<dim3(DIM / 64, ROWS / 64), 256>>>(src, DIM, mha_in_w + 2 * (size_t)DIM * DIM, DIM, mha_in_b + 2 * DIM, nullptr, cv, DIM, DIM, 0);

    // 10. cross attention
    attn_kernel<<<dim3(SEQ, BB * NH), 128>>>(cq, DIM, ck, DIM, cv, DIM, validL, att2, SEQ, LSEQ);

    // 11. upd = att2 @ mha_out_w^T + mha_out_b, scaled by rowvalid
    sgemm64<<<dim3(DIM / 64, ROWS / 64), 256>>>(att2, DIM, mha_out_w, DIM, mha_out_b, nullptr, upd, DIM, DIM, 0);
    scale_upd_kernel<<<(ROWS * DIM + 255) / 256, 256>>>(upd);

    // 12. gate pre-activation: tok2 @ gwA^T + upd @ gwB^T + gate_b
    sgemm64<<<dim3(DIM / 64, ROWS / 64), 256>>>(tok2, DIM, gate_w, 2 * DIM, nullptr, nullptr, gatep, DIM, DIM, 0);
    sgemm64<<<dim3(DIM / 64, ROWS / 64), 256>>>(upd, DIM, gate_w + DIM, 2 * DIM, gate_b, nullptr, gatep, DIM, DIM, 1);

    // 13. tok3 = tok2 + sigmoid(gatep)*upd
    gate_combine_kernel<<<(ROWS * DIM + 255) / 256, 256>>>(tok2, gatep, upd, tok3);

    // 14. FFN
    norm_film_kernel<<<ROWS, 256>>>(tok3, ffn_norm_w, nullptr, hbuf);
    sgemm64<<<dim3(2 * HIDDEN / 64, ROWS / 64), 256>>>(hbuf, DIM, gu_w, DIM, gu_b, nullptr, gu, 2 * HIDDEN, DIM, 0);
    silu_mul_kernel<<<(ROWS * HIDDEN + 255) / 256, 256>>>(gu, v2);
    sgemm64<<<dim3(DIM / 64, ROWS / 64), 256>>>(v2, HIDDEN, down_w, HIDDEN, down_b, tok3, out, DIM, HIDDEN, 0);
}

// round 10
// speedup vs baseline: 1.0003x; 1.0003x over previous
#include <cuda_runtime.h>
#include <math.h>
#include <stdint.h>

// ---------------- problem constants ----------------
#define BB      4
#define SEQ     1024
#define LSEQ    1024
#define DIM     1024
#define NH      16
#define HDIM    64
#define HIDDEN  4096
#define ROWS    (BB*SEQ)     // 4096

// ---------------- device scratch (no allocations allowed) ----------------
__device__ float g_x    [ROWS*DIM];
__device__ float g_qkv  [ROWS*3*DIM];
__device__ float g_attn [ROWS*DIM];
__device__ float g_tok2 [ROWS*DIM];
__device__ float g_query[ROWS*DIM];
__device__ float g_src  [ROWS*DIM];
__device__ float g_cq   [ROWS*DIM];
__device__ float g_ck   [ROWS*DIM];
__device__ float g_cv   [ROWS*DIM];
__device__ float g_att2 [ROWS*DIM];
__device__ float g_upd  [ROWS*DIM];
__device__ float g_gatep[ROWS*DIM];
__device__ float g_tok3 [ROWS*DIM];
__device__ float g_h    [ROWS*DIM];
__device__ float g_gu   [ROWS*2*HIDDEN];
__device__ float g_v2   [ROWS*HIDDEN];
__device__ float g_film [BB*2*DIM];
__device__ float g_validS[BB*SEQ];
__device__ float g_validL[BB*LSEQ];
__device__ float g_rowvalid[BB];
__device__ int   g_mask_mode;   // 0=uint8, 1=int32, 2=float32

// ---------------- mask dtype detection ----------------
// Inspect only first nbytes (= element count) bytes: safe lower bound for all dtypes.
__global__ void detect_mask_kernel(const unsigned char* p, int nbytes) {
    __shared__ int f_gt1, f_off;
    if (threadIdx.x == 0) { f_gt1 = 0; f_off = 0; }
    __syncthreads();
    for (int i = threadIdx.x; i < nbytes; i += blockDim.x) {
        unsigned char v = p[i];
        if (v > 1) atomicOr(&f_gt1, 1);
        else if (v == 1 && (i & 3)) atomicOr(&f_off, 1);
    }
    __syncthreads();
    if (threadIdx.x == 0) {
        g_mask_mode = f_gt1 ? 2 : (f_off ? 0 : 1);
    }
}

__device__ __forceinline__ int read_mask(const void* p, int idx, int mode) {
    if (mode == 0) return ((const unsigned char*)p)[idx] != 0;
    if (mode == 1) return ((const int*)p)[idx] != 0;
    return ((const float*)p)[idx] != 0.0f;
}

// valid[b*n+i] = ~safe_key_padding_mask(mask)[b,i]; rowvalid[b]=any(~mask[b]) (original mask)
__global__ void build_valid_kernel(const void* mask, int n, float* valid, float* rowvalid) {
    __shared__ int red[256];
    int b = blockIdx.x;
    int mode = g_mask_mode;
    int cnt = 0;
    for (int i = threadIdx.x; i < n; i += 256)
        cnt += read_mask(mask, b * n + i, mode);
    red[threadIdx.x] = cnt;
    __syncthreads();
    for (int s = 128; s > 0; s >>= 1) {
        if (threadIdx.x < s) red[threadIdx.x] += red[threadIdx.x + s];
        __syncthreads();
    }
    int allpad = (red[0] == n);
    for (int i = threadIdx.x; i < n; i += 256) {
        int m = read_mask(mask, b * n + i, mode);
        valid[b * n + i] = allpad ? 1.0f : (m ? 0.0f : 1.0f);
    }
    if (rowvalid && threadIdx.x == 0)
        rowvalid[b] = allpad ? 0.0f : 1.0f;
}

// ---------------- FiLM projection: out[b,j]=mod[b]·film_w[j]+film_b[j], j<2048 ----------------
__global__ void film_kernel(const float* __restrict__ mod, const float* __restrict__ w,
                            const float* __restrict__ bias, float* __restrict__ out) {
    int j = blockIdx.x * blockDim.x + threadIdx.x;
    int b = blockIdx.y;
    if (j >= 2 * DIM) return;
    const float* wr = w + (size_t)j * DIM;
    const float* mr = mod + (size_t)b * DIM;
    float s = bias[j];
    for (int k = 0; k < DIM; k++) s += mr[k] * wr[k];
    out[b * 2 * DIM + j] = s;
}

// ---------------- RMSNorm (+ optional FiLM) ----------------
__global__ void norm_film_kernel(const float* __restrict__ in, const float* __restrict__ w,
                                 const float* __restrict__ film, float* __restrict__ out) {
    __shared__ float red[256];
    int row = blockIdx.x;                 // 0..ROWS-1
    int b = row >> 10;                    // row / SEQ
    const float* x = in + (size_t)row * DIM;
    float ss = 0.0f;
    for (int d = threadIdx.x; d < DIM; d += 256) { float v = x[d]; ss += v * v; }
    red[threadIdx.x] = ss;
    __syncthreads();
    for (int s = 128; s > 0; s >>= 1) {
        if (threadIdx.x < s) red[threadIdx.x] += red[threadIdx.x + s];
        __syncthreads();
    }
    float r = rsqrtf(red[0] * (1.0f / DIM) + 1e-6f);
    for (int d = threadIdx.x; d < DIM; d += 256) {
        float v = x[d] * r * w[d];
        if (film) {
            float sc = 1.0f + 0.1f * tanhf(film[b * 2 * DIM + d]);
            v = v * sc + film[b * 2 * DIM + DIM + d];
        }
        out[(size_t)row * DIM + d] = v;
    }
}

// ---------------- SGEMM: C[M,N] = A[M,K] @ W[N,K]^T (+bias +res +accum) ----------------
// 64x64 tile, BK=16, 256 threads, 4x4 per thread.
__global__ void sgemm64(const float* __restrict__ A, int lda,
                        const float* __restrict__ W, int ldw,
                        const float* __restrict__ bias,
                        const float* __restrict__ res,
                        float* __restrict__ C, int ldc,
                        int K, int accum) {
    __shared__ float As[16][64];
    __shared__ float Ws[16][64];
    int row0 = blockIdx.y * 64;
    int col0 = blockIdx.x * 64;
    int tid = threadIdx.x;
    int tr = tid >> 4;          // 0..15
    int tc = tid & 15;          // 0..15
    int ar = tid >> 2;          // 0..63
    int ac = (tid & 3) * 4;     // 0,4,8,12

    float acc[4][4];
#pragma unroll
    for (int i = 0; i < 4; i++)
#pragma unroll
        for (int j = 0; j < 4; j++) acc[i][j] = 0.0f;

    for (int k0 = 0; k0 < K; k0 += 16) {
        float4 av = *reinterpret_cast<const float4*>(A + (size_t)(row0 + ar) * lda + k0 + ac);
        float4 wv = *reinterpret_cast<const float4*>(W + (size_t)(col0 + ar) * ldw + k0 + ac);
        As[ac + 0][ar] = av.x; As[ac + 1][ar] = av.y; As[ac + 2][ar] = av.z; As[ac + 3][ar] = av.w;
        Ws[ac + 0][ar] = wv.x; Ws[ac + 1][ar] = wv.y; Ws[ac + 2][ar] = wv.z; Ws[ac + 3][ar] = wv.w;
        __syncthreads();
#pragma unroll
        for (int kk = 0; kk < 16; kk++) {
            float4 a4 = *reinterpret_cast<const float4*>(&As[kk][tr * 4]);
            float4 b4 = *reinterpret_cast<const float4*>(&Ws[kk][tc * 4]);
            float a[4] = {a4.x, a4.y, a4.z, a4.w};
            float b[4] = {b4.x, b4.y, b4.z, b4.w};
#pragma unroll
            for (int i = 0; i < 4; i++)
#pragma unroll
                for (int j = 0; j < 4; j++) acc[i][j] += a[i] * b[j];
        }
        __syncthreads();
    }

#pragma unroll
    for (int i = 0; i < 4; i++) {
        int r = row0 + tr * 4 + i;
#pragma unroll
        for (int j = 0; j < 4; j++) {
            int c = col0 + tc * 4 + j;
            float v = acc[i][j];
            if (bias) v += bias[c];
            if (res) v += res[(size_t)r * ldc + c];
            if (accum) v += C[(size_t)r * ldc + c];
            C[(size_t)r * ldc + c] = v;
        }
    }
}

// ---------------- RoPE (in-place on q,k halves of g_qkv) ----------------
__global__ void rope_kernel(float* qkv) {
    int idx = blockIdx.x * blockDim.x + threadIdx.x;
    int total = BB * SEQ * NH * (HDIM / 2);
    if (idx >= total) return;
    int i = idx & 31;
    int h = (idx >> 5) & 15;
    int s = (idx >> 9) & 1023;
    int b = idx >> 19;
    float freq = expf((float)(2 * i) * (-0.14391156831212787f)); // -ln(10000)/64
    float ang = (float)s * freq;
    float sn, cs;
    sincosf(ang, &sn, &cs);
    size_t base = ((size_t)(b * SEQ + s)) * (3 * DIM) + h * HDIM + 2 * i;
    // q
    float e = qkv[base], o = qkv[base + 1];
    qkv[base] = e * cs - o * sn;
    qkv[base + 1] = e * sn + o * cs;
    // k
    size_t kb = base + DIM;
    e = qkv[kb]; o = qkv[kb + 1];
    qkv[kb] = e * cs - o * sn;
    qkv[kb + 1] = e * sn + o * cs;
}

// ---------------- attention: one block per (b,h,qi) ----------------
__global__ void attn_kernel(const float* __restrict__ Q, int qs,
                            const float* __restrict__ Kp, int ks,
                            const float* __restrict__ V, int vs,
                            const float* __restrict__ valid,
                            float* __restrict__ out,
                            int Sq, int Skv) {
    __shared__ float sc[1024];
    __shared__ float qv[HDIM];
    __shared__ float red[128];
    int qi = blockIdx.x;
    int bh = blockIdx.y;
    int b = bh / NH, h = bh % NH;
    int tid = threadIdx.x;

    const float* qrow = Q + ((size_t)(b * Sq + qi)) * qs + h * HDIM;
    if (tid < HDIM) qv[tid] = qrow[tid];
    __syncthreads();

    const float* kbase = Kp + ((size_t)b * Skv) * ks + h * HDIM;
    for (int t = tid; t < Skv; t += 128) {
        const float* kr = kbase + (size_t)t * ks;
        float s = 0.0f;
#pragma unroll
        for (int d = 0; d < HDIM; d += 4) {
            float4 kv4 = *reinterpret_cast<const float4*>(kr + d);
            s += qv[d] * kv4.x + qv[d + 1] * kv4.y + qv[d + 2] * kv4.z + qv[d + 3] * kv4.w;
        }
        s *= 0.125f;  // 1/sqrt(64)
        if (valid[b * Skv + t] == 0.0f) s = -1e30f;
        sc[t] = s;
    }
    __syncthreads();

    // max
    float m = -1e30f;
    for (int t = tid; t < Skv; t += 128) m = fmaxf(m, sc[t]);
    red[tid] = m;
    __syncthreads();
    for (int s = 64; s > 0; s >>= 1) {
        if (tid < s) red[tid] = fmaxf(red[tid], red[tid + s]);
        __syncthreads();
    }
    m = red[0];
    __syncthreads();

    // exp + sum
    float su = 0.0f;
    for (int t = tid; t < Skv; t += 128) {
        float e = expf(sc[t] - m);
        sc[t] = e;
        su += e;
    }
    red[tid] = su;
    __syncthreads();
    for (int s = 64; s > 0; s >>= 1) {
        if (tid < s) red[tid] += red[tid + s];
        __syncthreads();
    }
    float inv = 1.0f / red[0];
    __syncthreads();

    // AV
    int d = tid & 63;
    int half = tid >> 6;
    const float* vbase = V + ((size_t)b * Skv) * vs + h * HDIM + d;
    float accv = 0.0f;
    int t0 = half * (Skv / 2), t1 = t0 + (Skv / 2);
#pragma unroll 4
    for (int t = t0; t < t1; t++) accv += sc[t] * vbase[(size_t)t * vs];
    red[tid] = accv;
    __syncthreads();
    if (tid < 64) {
        float r = (red[tid] + red[tid + 64]) * inv;
        out[((size_t)(b * Sq + qi)) * DIM + h * HDIM + d] = r;
    }
}

// ---------------- elementwise ----------------
__global__ void scale_upd_kernel(float* upd) {
    int i = blockIdx.x * blockDim.x + threadIdx.x;
    if (i >= ROWS * DIM) return;
    upd[i] *= g_rowvalid[i >> 20];   // SEQ*DIM = 2^20 elements per batch
}

__global__ void gate_combine_kernel(const float* __restrict__ tok2, const float* __restrict__ gatep,
                                    const float* __restrict__ upd, float* __restrict__ tok3) {
    int i = blockIdx.x * blockDim.x + threadIdx.x;
    if (i >= ROWS * DIM) return;
    float g = 1.0f / (1.0f + expf(-gatep[i]));
    tok3[i] = tok2[i] + g * upd[i];
}

__global__ void silu_mul_kernel(const float* __restrict__ gu, float* __restrict__ v2) {
    int i = blockIdx.x * blockDim.x + threadIdx.x;
    if (i >= ROWS * HIDDEN) return;
    int m = i >> 12;          // row
    int j = i & 4095;         // col within HIDDEN
    float g = gu[(size_t)m * 2 * HIDDEN + j];
    float val = gu[(size_t)m * 2 * HIDDEN + HIDDEN + j];
    float sg = g / (1.0f + expf(-g));
    v2[i] = sg * val;
}

// ---------------- host launch ----------------
static float* symf(const void* devsym) {
    void* p = nullptr;
    cudaGetSymbolAddress(&p, devsym);
    return (float*)p;
}

extern "C" void kernel_launch(void* const* d_in, const int* in_sizes, int n_in,
                              void* d_out, int out_size) {
    const float* tokens     = (const float*)d_in[0];
    const float* seq_tokens = (const float*)d_in[1];
    const float* modulation = (const float*)d_in[2];
    const float* attn_norm_w= (const float*)d_in[3];
    const float* qkv_w      = (const float*)d_in[4];
    const float* qkv_b      = (const float*)d_in[5];
    const float* out_w      = (const float*)d_in[6];
    const float* out_b      = (const float*)d_in[7];
    const float* film_w     = (const float*)d_in[8];
    const float* film_b     = (const float*)d_in[9];
    const float* sq_norm_w  = (const float*)d_in[10];
    const float* s_norm_w   = (const float*)d_in[11];
    const float* mha_in_w   = (const float*)d_in[12];
    const float* mha_in_b   = (const float*)d_in[13];
    const float* mha_out_w  = (const float*)d_in[14];
    const float* mha_out_b  = (const float*)d_in[15];
    const float* gate_w     = (const float*)d_in[16];
    const float* gate_b     = (const float*)d_in[17];
    const float* ffn_norm_w = (const float*)d_in[18];
    const float* gu_w       = (const float*)d_in[19];
    const float* gu_b       = (const float*)d_in[20];
    const float* down_w     = (const float*)d_in[21];
    const float* down_b     = (const float*)d_in[22];
    const void*  padding_mask = d_in[23];
    const void*  seq_mask     = d_in[24];
    float* out = (float*)d_out;

    float* x     = symf(g_x);
    float* qkv   = symf(g_qkv);
    float* attn  = symf(g_attn);
    float* tok2  = symf(g_tok2);
    float* query = symf(g_query);
    float* src   = symf(g_src);
    float* cq    = symf(g_cq);
    float* ck    = symf(g_ck);
    float* cv    = symf(g_cv);
    float* att2  = symf(g_att2);
    float* upd   = symf(g_upd);
    float* gatep = symf(g_gatep);
    float* tok3  = symf(g_tok3);
    float* hbuf  = symf(g_h);
    float* gu    = symf(g_gu);
    float* v2    = symf(g_v2);
    float* film  = symf(g_film);
    float* validS= symf(g_validS);
    float* validL= symf(g_validL);
    float* rowv  = symf(g_rowvalid);

    // 1. mask dtype detection + valid arrays
    detect_mask_kernel<<<1, 256>>>((const unsigned char*)padding_mask, BB * SEQ);
    build_valid_kernel<<<BB, 256>>>(padding_mask, SEQ, validS, nullptr);
    build_valid_kernel<<<BB, 256>>>(seq_mask, LSEQ, validL, rowv);

    // 2. FiLM projection
    {
        dim3 grid((2 * DIM + 127) / 128, BB);
        film_kernel<<<grid, 128>>>(modulation, film_w, film_b, film);
    }

    // 3. rmsnorm + film -> x
    norm_film_kernel<<<ROWS, 256>>>(tokens, attn_norm_w, film, x);

    // 4. qkv = x @ qkv_w^T + qkv_b
    sgemm64<<<dim3(3 * DIM / 64, ROWS / 64), 256>>>(x, DIM, qkv_w, DIM, qkv_b, nullptr, qkv, 3 * DIM, DIM, 0);

    // 5. rope in place
    {
        int total = BB * SEQ * NH * (HDIM / 2);
        rope_kernel<<<(total + 255) / 256, 256>>>(qkv);
    }

    // 6. self attention -> attn (merged heads)
    attn_kernel<<<dim3(SEQ, BB * NH), 128>>>(qkv, 3 * DIM, qkv + DIM, 3 * DIM, qkv + 2 * DIM, 3 * DIM,
                                             validS, attn, SEQ, SEQ);

    // 7. tok2 = tokens + attn @ out_w^T + out_b
    sgemm64<<<dim3(DIM / 64, ROWS / 64), 256>>>(attn, DIM, out_w, DIM, out_b, tokens, tok2, DIM, DIM, 0);

    // 8. norms
    norm_film_kernel<<<ROWS, 256>>>(tok2, sq_norm_w, nullptr, query);
    norm_film_kernel<<<ROWS, 256>>>(seq_tokens, s_norm_w, nullptr, src);

    // 9. cross q/k/v
    sgemm64<<<dim3(DIM / 64, ROWS / 64), 256>>>(query, DIM, mha_in_w, DIM, mha_in_b, nullptr, cq, DIM, DIM, 0);
    sgemm64<<<dim3(DIM / 64, ROWS / 64), 256>>>(src, DIM, mha_in_w + (size_t)DIM * DIM, DIM, mha_in_b + DIM, nullptr, ck, DIM, DIM, 0);
    sgemm64<<<dim3(DIM / 64, ROWS / 64), 256>>>(src, DIM, mha_in_w + 2 * (size_t)DIM * DIM, DIM, mha_in_b + 2 * DIM, nullptr, cv, DIM, DIM, 0);

    // 10. cross attention
    attn_kernel<<<dim3(SEQ, BB * NH), 128>>>(cq, DIM, ck, DIM, cv, DIM, validL, att2, SEQ, LSEQ);

    // 11. upd = att2 @ mha_out_w^T + mha_out_b, scaled by rowvalid
    sgemm64<<<dim3(DIM / 64, ROWS / 64), 256>>>(att2, DIM, mha_out_w, DIM, mha_out_b, nullptr, upd, DIM, DIM, 0);
    scale_upd_kernel<<<(ROWS * DIM + 255) / 256, 256>>>(upd);

    // 12. gate pre-activation: tok2 @ gwA^T + upd @ gwB^T + gate_b
    sgemm64<<<dim3(DIM / 64, ROWS / 64), 256>>>(tok2, DIM, gate_w, 2 * DIM, nullptr, nullptr, gatep, DIM, DIM, 0);
    sgemm64<<<dim3(DIM / 64, ROWS / 64), 256>>>(upd, DIM, gate_w + DIM, 2 * DIM, gate_b, nullptr, gatep, DIM, DIM, 1);

    // 13. tok3 = tok2 + sigmoid(gatep)*upd
    gate_combine_kernel<<<(ROWS * DIM + 255) / 256, 256>>>(tok2, gatep, upd, tok3);

    // 14. FFN
    norm_film_kernel<<<ROWS, 256>>>(tok3, ffn_norm_w, nullptr, hbuf);
    sgemm64<<<dim3(2 * HIDDEN / 64, ROWS / 64), 256>>>(hbuf, DIM, gu_w, DIM, gu_b, nullptr, gu, 2 * HIDDEN, DIM, 0);
    silu_mul_kernel<<<(ROWS * HIDDEN + 255) / 256, 256>>>(gu, v2);
    sgemm64<<<dim3(DIM / 64, ROWS / 64), 256>>>(v2, HIDDEN, down_w, HIDDEN, down_b, tok3, out, DIM, HIDDEN, 0);
}

// round 12
// speedup vs baseline: 3.3077x; 3.3067x over previous
#include <cuda_runtime.h>
#include <math.h>
#include <stdint.h>

// ---------------- problem constants ----------------
#define BB      4
#define SEQ     1024
#define LSEQ    1024
#define DIM     1024
#define NH      16
#define HDIM    64
#define HIDDEN  4096
#define ROWS    (BB*SEQ)     // 4096

// ---------------- device scratch ----------------
__device__ float g_x    [ROWS*DIM];
__device__ float g_qkv  [ROWS*3*DIM];     // also reused as [ck|cv] (ldc=2048) for cross attn
__device__ float g_attn [ROWS*DIM];
__device__ float g_tok2 [ROWS*DIM];
__device__ float g_query[ROWS*DIM];
__device__ float g_src  [ROWS*DIM];
__device__ float g_cq   [ROWS*DIM];
__device__ float g_att2 [ROWS*DIM];
__device__ float g_upd  [ROWS*DIM];
__device__ float g_gatep[ROWS*DIM];       // gate preact, then overwritten with tok3
__device__ float g_h    [ROWS*DIM];
__device__ float g_gu   [ROWS*2*HIDDEN];
__device__ float g_v2   [ROWS*HIDDEN];
__device__ float g_film [BB*2*DIM];
__device__ float g_validS[BB*SEQ];
__device__ float g_validL[BB*LSEQ];
__device__ float g_rowvalid[BB];
__device__ int   g_mask_mode;   // 0=uint8, 1=int32, 2=float32

// ---------------- mask dtype detection ----------------
__global__ void detect_mask_kernel(const unsigned char* p, int nbytes) {
    __shared__ int f_gt1, f_off;
    if (threadIdx.x == 0) { f_gt1 = 0; f_off = 0; }
    __syncthreads();
    for (int i = threadIdx.x; i < nbytes; i += blockDim.x) {
        unsigned char v = p[i];
        if (v > 1) atomicOr(&f_gt1, 1);
        else if (v == 1 && (i & 3)) atomicOr(&f_off, 1);
    }
    __syncthreads();
    if (threadIdx.x == 0) g_mask_mode = f_gt1 ? 2 : (f_off ? 0 : 1);
}

__device__ __forceinline__ int read_mask(const void* p, int idx, int mode) {
    if (mode == 0) return ((const unsigned char*)p)[idx] != 0;
    if (mode == 1) return ((const int*)p)[idx] != 0;
    return ((const float*)p)[idx] != 0.0f;
}

__global__ void build_valid_kernel(const void* mask, int n, float* valid, float* rowvalid) {
    __shared__ int red[256];
    int b = blockIdx.x;
    int mode = g_mask_mode;
    int cnt = 0;
    for (int i = threadIdx.x; i < n; i += 256)
        cnt += read_mask(mask, b * n + i, mode);
    red[threadIdx.x] = cnt;
    __syncthreads();
    for (int s = 128; s > 0; s >>= 1) {
        if (threadIdx.x < s) red[threadIdx.x] += red[threadIdx.x + s];
        __syncthreads();
    }
    int allpad = (red[0] == n);
    for (int i = threadIdx.x; i < n; i += 256) {
        int m = read_mask(mask, b * n + i, mode);
        valid[b * n + i] = allpad ? 1.0f : (m ? 0.0f : 1.0f);
    }
    if (rowvalid && threadIdx.x == 0)
        rowvalid[b] = allpad ? 0.0f : 1.0f;
}

// ---------------- FiLM: warp per output ----------------
__global__ void film_kernel(const float* __restrict__ mod, const float* __restrict__ w,
                            const float* __restrict__ bias, float* __restrict__ out) {
    int warp = threadIdx.x >> 5, lane = threadIdx.x & 31;
    int j = blockIdx.x * 8 + warp;   // output index 0..2047
    int b = blockIdx.y;
    const float* wr = w + (size_t)j * DIM;
    const float* mr = mod + (size_t)b * DIM;
    float s = 0.0f;
#pragma unroll
    for (int k = lane * 4; k < DIM; k += 128) {
        float4 wv = *(const float4*)(wr + k);
        float4 mv = *(const float4*)(mr + k);
        s += wv.x * mv.x + wv.y * mv.y + wv.z * mv.z + wv.w * mv.w;
    }
#pragma unroll
    for (int o = 16; o > 0; o >>= 1) s += __shfl_xor_sync(0xffffffffu, s, o);
    if (lane == 0) out[b * 2 * DIM + j] = s + bias[j];
}

// ---------------- RMSNorm (+optional FiLM), float4, 256 thr/row ----------------
__global__ void norm_film_kernel(const float* __restrict__ in, const float* __restrict__ w,
                                 const float* __restrict__ film, float* __restrict__ out) {
    __shared__ float red[8];
    int row = blockIdx.x;
    int b = row >> 10;
    int t = threadIdx.x;
    float4 v = ((const float4*)(in + (size_t)row * DIM))[t];
    float ss = v.x * v.x + v.y * v.y + v.z * v.z + v.w * v.w;
#pragma unroll
    for (int o = 16; o > 0; o >>= 1) ss += __shfl_xor_sync(0xffffffffu, ss, o);
    if ((t & 31) == 0) red[t >> 5] = ss;
    __syncthreads();
    if (t < 8) {
        float s = red[t];
#pragma unroll
        for (int o = 4; o > 0; o >>= 1) s += __shfl_xor_sync(0xffu, s, o, 8);
        if (t == 0) red[0] = s;
    }
    __syncthreads();
    float r = rsqrtf(red[0] * (1.0f / DIM) + 1e-6f);
    float4 wv = ((const float4*)w)[t];
    float4 o4;
    o4.x = v.x * r * wv.x; o4.y = v.y * r * wv.y;
    o4.z = v.z * r * wv.z; o4.w = v.w * r * wv.w;
    if (film) {
        float4 sc = ((const float4*)(film + b * 2 * DIM))[t];
        float4 sh = ((const float4*)(film + b * 2 * DIM + DIM))[t];
        o4.x = o4.x * (1.0f + 0.1f * tanhf(sc.x)) + sh.x;
        o4.y = o4.y * (1.0f + 0.1f * tanhf(sc.y)) + sh.y;
        o4.z = o4.z * (1.0f + 0.1f * tanhf(sc.z)) + sh.z;
        o4.w = o4.w * (1.0f + 0.1f * tanhf(sc.w)) + sh.w;
    }
    ((float4*)(out + (size_t)row * DIM))[t] = o4;
}

// ---------------- SGEMM: C[M,N] = A[M,K] @ W[N,K]^T, 128x128x16, 8x8/thread ----------------
// epi=0: v=acc(+bias)(+accum C)(+res);  epi=1: v=(acc+bias)*aux[r>>10];
// epi=2: v=res + sigmoid(acc+bias+accum C)*aux  (gate fusion)
__global__ void __launch_bounds__(256, 2) sgemm128(
    const float* __restrict__ A, int lda,
    const float* __restrict__ W, int ldw,
    const float* __restrict__ bias,
    const float* __restrict__ res,
    const float* __restrict__ aux,
    float* __restrict__ C, int ldc,
    int K, int accum, int epi)
{
    __shared__ float As[2][16][132];
    __shared__ float Ws[2][16][132];

    int row0 = blockIdx.y * 128, col0 = blockIdx.x * 128;
    int tid = threadIdx.x;
    int ty = tid >> 4, tx = tid & 15;
    int lr = tid >> 1, lc = (tid & 1) * 8;

    const float* Aptr = A + (size_t)(row0 + lr) * lda + lc;
    const float* Wptr = W + (size_t)(col0 + lr) * ldw + lc;

    // stage 0
    {
        float4 a0 = *(const float4*)(Aptr);
        float4 a1 = *(const float4*)(Aptr + 4);
        float4 w0 = *(const float4*)(Wptr);
        float4 w1 = *(const float4*)(Wptr + 4);
        As[0][lc + 0][lr] = a0.x; As[0][lc + 1][lr] = a0.y; As[0][lc + 2][lr] = a0.z; As[0][lc + 3][lr] = a0.w;
        As[0][lc + 4][lr] = a1.x; As[0][lc + 5][lr] = a1.y; As[0][lc + 6][lr] = a1.z; As[0][lc + 7][lr] = a1.w;
        Ws[0][lc + 0][lr] = w0.x; Ws[0][lc + 1][lr] = w0.y; Ws[0][lc + 2][lr] = w0.z; Ws[0][lc + 3][lr] = w0.w;
        Ws[0][lc + 4][lr] = w1.x; Ws[0][lc + 5][lr] = w1.y; Ws[0][lc + 6][lr] = w1.z; Ws[0][lc + 7][lr] = w1.w;
    }
    __syncthreads();

    float acc[8][8];
#pragma unroll
    for (int i = 0; i < 8; i++)
#pragma unroll
        for (int j = 0; j < 8; j++) acc[i][j] = 0.0f;

    int nt = K >> 4;
    for (int t = 0; t < nt; t++) {
        int cur = t & 1;
        float4 na0, na1, nw0, nw1;
        if (t + 1 < nt) {
            const float* Ap = Aptr + (t + 1) * 16;
            const float* Wp = Wptr + (t + 1) * 16;
            na0 = *(const float4*)(Ap);
            na1 = *(const float4*)(Ap + 4);
            nw0 = *(const float4*)(Wp);
            nw1 = *(const float4*)(Wp + 4);
        }
#pragma unroll
        for (int kk = 0; kk < 16; kk++) {
            float4 x0 = *(const float4*)&As[cur][kk][ty * 8];
            float4 x1 = *(const float4*)&As[cur][kk][ty * 8 + 4];
            float4 y0 = *(const float4*)&Ws[cur][kk][tx * 8];
            float4 y1 = *(const float4*)&Ws[cur][kk][tx * 8 + 4];
            float a[8] = {x0.x, x0.y, x0.z, x0.w, x1.x, x1.y, x1.z, x1.w};
            float b[8] = {y0.x, y0.y, y0.z, y0.w, y1.x, y1.y, y1.z, y1.w};
#pragma unroll
            for (int i = 0; i < 8; i++)
#pragma unroll
                for (int j = 0; j < 8; j++) acc[i][j] += a[i] * b[j];
        }
        if (t + 1 < nt) {
            int nx = cur ^ 1;
            As[nx][lc + 0][lr] = na0.x; As[nx][lc + 1][lr] = na0.y; As[nx][lc + 2][lr] = na0.z; As[nx][lc + 3][lr] = na0.w;
            As[nx][lc + 4][lr] = na1.x; As[nx][lc + 5][lr] = na1.y; As[nx][lc + 6][lr] = na1.z; As[nx][lc + 7][lr] = na1.w;
            Ws[nx][lc + 0][lr] = nw0.x; Ws[nx][lc + 1][lr] = nw0.y; Ws[nx][lc + 2][lr] = nw0.z; Ws[nx][lc + 3][lr] = nw0.w;
            Ws[nx][lc + 4][lr] = nw1.x; Ws[nx][lc + 5][lr] = nw1.y; Ws[nx][lc + 6][lr] = nw1.z; Ws[nx][lc + 7][lr] = nw1.w;
            __syncthreads();
        }
    }

#pragma unroll
    for (int i = 0; i < 8; i++) {
        int r = row0 + ty * 8 + i;
        size_t rb = (size_t)r * ldc;
#pragma unroll
        for (int j0 = 0; j0 < 8; j0 += 4) {
            int c = col0 + tx * 8 + j0;
            float4 v = make_float4(acc[i][j0], acc[i][j0 + 1], acc[i][j0 + 2], acc[i][j0 + 3]);
            if (bias) {
                float4 bv = *(const float4*)(bias + c);
                v.x += bv.x; v.y += bv.y; v.z += bv.z; v.w += bv.w;
            }
            if (accum) {
                float4 cv = *(const float4*)(C + rb + c);
                v.x += cv.x; v.y += cv.y; v.z += cv.z; v.w += cv.w;
            }
            if (epi == 2) {
                float4 rv = *(const float4*)(res + rb + c);
                float4 av = *(const float4*)(aux + rb + c);
                v.x = rv.x + av.x / (1.0f + expf(-v.x));
                v.y = rv.y + av.y / (1.0f + expf(-v.y));
                v.z = rv.z + av.z / (1.0f + expf(-v.z));
                v.w = rv.w + av.w / (1.0f + expf(-v.w));
            } else {
                if (res) {
                    float4 rv = *(const float4*)(res + rb + c);
                    v.x += rv.x; v.y += rv.y; v.z += rv.z; v.w += rv.w;
                }
                if (epi == 1) {
                    float s = aux[r >> 10];
                    v.x *= s; v.y *= s; v.z *= s; v.w *= s;
                }
            }
            *(float4*)(C + rb + c) = v;
        }
    }
}

// ---------------- RoPE (in-place on q,k halves of g_qkv) ----------------
__global__ void rope_kernel(float* qkv) {
    int idx = blockIdx.x * blockDim.x + threadIdx.x;
    int total = BB * SEQ * NH * (HDIM / 2);
    if (idx >= total) return;
    int i = idx & 31;
    int h = (idx >> 5) & 15;
    int s = (idx >> 9) & 1023;
    int b = idx >> 19;
    float freq = expf((float)(2 * i) * (-0.14391156831212787f)); // -ln(10000)/64
    float ang = (float)s * freq;
    float sn, cs;
    sincosf(ang, &sn, &cs);
    size_t base = ((size_t)(b * SEQ + s)) * (3 * DIM) + h * HDIM + 2 * i;
    float e = qkv[base], o = qkv[base + 1];
    qkv[base] = e * cs - o * sn;
    qkv[base + 1] = e * sn + o * cs;
    size_t kb = base + DIM;
    e = qkv[kb]; o = qkv[kb + 1];
    qkv[kb] = e * cs - o * sn;
    qkv[kb + 1] = e * sn + o * cs;
}

// ---------------- flash attention: 64 queries x 64 keys tiles ----------------
// grid (SEQ/64, BB*NH), 256 threads. out has merged-head layout, row stride DIM.
#define FA_PITCH 68
__global__ void __launch_bounds__(256) fattn(
    const float* __restrict__ Q, int qs,
    const float* __restrict__ Kp, int ks,
    const float* __restrict__ V, int vs,
    const float* __restrict__ valid,
    float* __restrict__ out, int Skv)
{
    extern __shared__ float sh[];
    float (*Qt)[FA_PITCH] = (float(*)[FA_PITCH])sh;
    float (*Kt)[FA_PITCH] = (float(*)[FA_PITCH])(sh + 64 * FA_PITCH);
    float (*Vs)[FA_PITCH] = (float(*)[FA_PITCH])(sh + 2 * 64 * FA_PITCH);
    float (*Ss)[FA_PITCH] = (float(*)[FA_PITCH])(sh + 3 * 64 * FA_PITCH);

    int q0 = blockIdx.x * 64;
    int bh = blockIdx.y;
    int b = bh >> 4, h = bh & 15;
    int tid = threadIdx.x, ty = tid >> 4, tx = tid & 15;

    // load Q tile transposed: Qt[d][q]
    const float* Qbase = Q + ((size_t)(b * SEQ + q0)) * qs + h * HDIM;
#pragma unroll
    for (int r = 0; r < 4; r++) {
        int slot = tid + r * 256;
        int q = slot >> 4, d4 = (slot & 15) * 4;
        float4 v = *(const float4*)(Qbase + (size_t)q * qs + d4);
        Qt[d4 + 0][q] = v.x; Qt[d4 + 1][q] = v.y; Qt[d4 + 2][q] = v.z; Qt[d4 + 3][q] = v.w;
    }

    float m[4], l[4], O[4][4];
#pragma unroll
    for (int i = 0; i < 4; i++) {
        m[i] = -3.0e38f; l[i] = 0.0f;
#pragma unroll
        for (int j = 0; j < 4; j++) O[i][j] = 0.0f;
    }

    const float* Kbase = Kp + (size_t)b * Skv * ks + h * HDIM;
    const float* Vbase = V + (size_t)b * Skv * vs + h * HDIM;
    const float* vb = valid + b * Skv;

    for (int k0 = 0; k0 < Skv; k0 += 64) {
        __syncthreads();   // protects Kt/Vs/Ss from previous iteration; orders Qt on first iter
#pragma unroll
        for (int r = 0; r < 4; r++) {
            int slot = tid + r * 256;
            int kr = slot >> 4, d4 = (slot & 15) * 4;
            float4 kv = *(const float4*)(Kbase + (size_t)(k0 + kr) * ks + d4);
            Kt[d4 + 0][kr] = kv.x; Kt[d4 + 1][kr] = kv.y; Kt[d4 + 2][kr] = kv.z; Kt[d4 + 3][kr] = kv.w;
            float4 vv = *(const float4*)(Vbase + (size_t)(k0 + kr) * vs + d4);
            *(float4*)&Vs[kr][d4] = vv;
        }
        __syncthreads();

        // S = Q K^T  (4x4 per thread)
        float s[4][4];
#pragma unroll
        for (int i = 0; i < 4; i++)
#pragma unroll
            for (int j = 0; j < 4; j++) s[i][j] = 0.0f;
#pragma unroll
        for (int d = 0; d < 64; d++) {
            float4 a4 = *(const float4*)&Qt[d][ty * 4];
            float4 b4 = *(const float4*)&Kt[d][tx * 4];
            float a[4] = {a4.x, a4.y, a4.z, a4.w};
            float bb2[4] = {b4.x, b4.y, b4.z, b4.w};
#pragma unroll
            for (int i = 0; i < 4; i++)
#pragma unroll
                for (int j = 0; j < 4; j++) s[i][j] += a[i] * bb2[j];
        }
        // scale + mask
        float vm[4];
#pragma unroll
        for (int j = 0; j < 4; j++) vm[j] = vb[k0 + tx * 4 + j];
#pragma unroll
        for (int i = 0; i < 4; i++)
#pragma unroll
            for (int j = 0; j < 4; j++)
                s[i][j] = (vm[j] != 0.0f) ? s[i][j] * 0.125f : -1e30f;

        // row max across 16 lanes (row group = half warp)
        float mt[4];
#pragma unroll
        for (int i = 0; i < 4; i++)
            mt[i] = fmaxf(fmaxf(s[i][0], s[i][1]), fmaxf(s[i][2], s[i][3]));
#pragma unroll
        for (int o = 8; o > 0; o >>= 1)
#pragma unroll
            for (int i = 0; i < 4; i++)
                mt[i] = fmaxf(mt[i], __shfl_xor_sync(0xffffffffu, mt[i], o, 16));

        float fac[4], rs[4];
#pragma unroll
        for (int i = 0; i < 4; i++) {
            float mn = fmaxf(m[i], mt[i]);
            fac[i] = expf(m[i] - mn);
            m[i] = mn;
            rs[i] = 0.0f;
        }
#pragma unroll
        for (int i = 0; i < 4; i++)
#pragma unroll
            for (int j = 0; j < 4; j++) {
                float p = expf(s[i][j] - m[i]);
                s[i][j] = p;
                rs[i] += p;
            }
#pragma unroll
        for (int o = 8; o > 0; o >>= 1)
#pragma unroll
            for (int i = 0; i < 4; i++)
                rs[i] += __shfl_xor_sync(0xffffffffu, rs[i], o, 16);
#pragma unroll
        for (int i = 0; i < 4; i++) {
            l[i] = l[i] * fac[i] + rs[i];
#pragma unroll
            for (int j = 0; j < 4; j++) O[i][j] *= fac[i];
        }
        // stash P
#pragma unroll
        for (int i = 0; i < 4; i++)
            *(float4*)&Ss[ty * 4 + i][tx * 4] = make_float4(s[i][0], s[i][1], s[i][2], s[i][3]);
        __syncthreads();

        // O += P V
#pragma unroll
        for (int k = 0; k < 64; k++) {
            float4 v4 = *(const float4*)&Vs[k][tx * 4];
            float vv[4] = {v4.x, v4.y, v4.z, v4.w};
#pragma unroll
            for (int i = 0; i < 4; i++) {
                float p = Ss[ty * 4 + i][k];
#pragma unroll
                for (int j = 0; j < 4; j++) O[i][j] += p * vv[j];
            }
        }
    }

    // write out
#pragma unroll
    for (int i = 0; i < 4; i++) {
        float inv = 1.0f / l[i];
        float* ob = out + ((size_t)(b * SEQ + q0 + ty * 4 + i)) * DIM + h * HDIM + tx * 4;
        *(float4*)ob = make_float4(O[i][0] * inv, O[i][1] * inv, O[i][2] * inv, O[i][3] * inv);
    }
}

// ---------------- SiLU * val (float4) ----------------
__global__ void silu_mul_kernel(const float* __restrict__ gu, float* __restrict__ v2) {
    int i = blockIdx.x * blockDim.x + threadIdx.x;   // float4 index
    if (i >= ROWS * HIDDEN / 4) return;
    int row = i >> 10;              // HIDDEN/4 = 1024 float4 per row
    int j = i & 1023;
    const float4* gp = (const float4*)(gu + (size_t)row * 2 * HIDDEN);
    float4 g = gp[j];
    float4 val = gp[j + 1024];
    float4 o;
    o.x = (g.x / (1.0f + expf(-g.x))) * val.x;
    o.y = (g.y / (1.0f + expf(-g.y))) * val.y;
    o.z = (g.z / (1.0f + expf(-g.z))) * val.z;
    o.w = (g.w / (1.0f + expf(-g.w))) * val.w;
    ((float4*)v2)[i] = o;
}

// ---------------- host launch ----------------
static float* symf(const void* devsym) {
    void* p = nullptr;
    cudaGetSymbolAddress(&p, devsym);
    return (float*)p;
}

extern "C" void kernel_launch(void* const* d_in, const int* in_sizes, int n_in,
                              void* d_out, int out_size) {
    const float* tokens     = (const float*)d_in[0];
    const float* seq_tokens = (const float*)d_in[1];
    const float* modulation = (const float*)d_in[2];
    const float* attn_norm_w= (const float*)d_in[3];
    const float* qkv_w      = (const float*)d_in[4];
    const float* qkv_b      = (const float*)d_in[5];
    const float* out_w      = (const float*)d_in[6];
    const float* out_b      = (const float*)d_in[7];
    const float* film_w     = (const float*)d_in[8];
    const float* film_b     = (const float*)d_in[9];
    const float* sq_norm_w  = (const float*)d_in[10];
    const float* s_norm_w   = (const float*)d_in[11];
    const float* mha_in_w   = (const float*)d_in[12];
    const float* mha_in_b   = (const float*)d_in[13];
    const float* mha_out_w  = (const float*)d_in[14];
    const float* mha_out_b  = (const float*)d_in[15];
    const float* gate_w     = (const float*)d_in[16];
    const float* gate_b     = (const float*)d_in[17];
    const float* ffn_norm_w = (const float*)d_in[18];
    const float* gu_w       = (const float*)d_in[19];
    const float* gu_b       = (const float*)d_in[20];
    const float* down_w     = (const float*)d_in[21];
    const float* down_b     = (const float*)d_in[22];
    const void*  padding_mask = d_in[23];
    const void*  seq_mask     = d_in[24];
    float* out = (float*)d_out;

    float* x     = symf(g_x);
    float* qkv   = symf(g_qkv);
    float* attn  = symf(g_attn);
    float* tok2  = symf(g_tok2);
    float* query = symf(g_query);
    float* src   = symf(g_src);
    float* cq    = symf(g_cq);
    float* att2  = symf(g_att2);
    float* upd   = symf(g_upd);
    float* gatep = symf(g_gatep);
    float* hbuf  = symf(g_h);
    float* gu    = symf(g_gu);
    float* v2    = symf(g_v2);
    float* film  = symf(g_film);
    float* validS= symf(g_validS);
    float* validL= symf(g_validL);
    float* rowv  = symf(g_rowvalid);

    static int fattn_smem_set = 0;
    const int FA_SMEM = 4 * 64 * FA_PITCH * sizeof(float);
    if (!fattn_smem_set) {
        cudaFuncSetAttribute(fattn, cudaFuncAttributeMaxDynamicSharedMemorySize, FA_SMEM);
        fattn_smem_set = 1;
    }

    // masks
    detect_mask_kernel<<<1, 256>>>((const unsigned char*)padding_mask, BB * SEQ);
    build_valid_kernel<<<BB, 256>>>(padding_mask, SEQ, validS, nullptr);
    build_valid_kernel<<<BB, 256>>>(seq_mask, LSEQ, validL, rowv);

    // FiLM projection (warp/output)
    film_kernel<<<dim3(2 * DIM / 8, BB), 256>>>(modulation, film_w, film_b, film);

    // rmsnorm + film -> x
    norm_film_kernel<<<ROWS, 256>>>(tokens, attn_norm_w, film, x);

    // qkv = x @ qkv_w^T + qkv_b
    sgemm128<<<dim3(3 * DIM / 128, ROWS / 128), 256>>>(x, DIM, qkv_w, DIM, qkv_b, nullptr, nullptr, qkv, 3 * DIM, DIM, 0, 0);

    // rope in place
    {
        int total = BB * SEQ * NH * (HDIM / 2);
        rope_kernel<<<(total + 255) / 256, 256>>>(qkv);
    }

    // self attention
    fattn<<<dim3(SEQ / 64, BB * NH), 256, FA_SMEM>>>(qkv, 3 * DIM, qkv + DIM, 3 * DIM, qkv + 2 * DIM, 3 * DIM,
                                                     validS, attn, SEQ);

    // tok2 = tokens + attn @ out_w^T + out_b
    sgemm128<<<dim3(DIM / 128, ROWS / 128), 256>>>(attn, DIM, out_w, DIM, out_b, tokens, nullptr, tok2, DIM, DIM, 0, 0);

    // norms
    norm_film_kernel<<<ROWS, 256>>>(tok2, sq_norm_w, nullptr, query);
    norm_film_kernel<<<ROWS, 256>>>(seq_tokens, s_norm_w, nullptr, src);

    // cross q
    sgemm128<<<dim3(DIM / 128, ROWS / 128), 256>>>(query, DIM, mha_in_w, DIM, mha_in_b, nullptr, nullptr, cq, DIM, DIM, 0, 0);
    // cross k|v fused into one GEMM (N=2048), reusing g_qkv as [ck|cv] with ldc 2048
    sgemm128<<<dim3(2 * DIM / 128, ROWS / 128), 256>>>(src, DIM, mha_in_w + (size_t)DIM * DIM, DIM,
                                                       mha_in_b + DIM, nullptr, nullptr, qkv, 2 * DIM, DIM, 0, 0);

    // cross attention
    fattn<<<dim3(SEQ / 64, BB * NH), 256, FA_SMEM>>>(cq, DIM, qkv, 2 * DIM, qkv + DIM, 2 * DIM,
                                                     validL, att2, LSEQ);

    // upd = (att2 @ mha_out_w^T + b) * rowvalid  (epi=1 fusion)
    sgemm128<<<dim3(DIM / 128, ROWS / 128), 256>>>(att2, DIM, mha_out_w, DIM, mha_out_b, nullptr, rowv, upd, DIM, DIM, 0, 1);

    // gate: gatep = tok2 @ gwA^T; then tok3 = tok2 + sigmoid(gatep + upd @ gwB^T + b) * upd  (epi=2 fusion)
    sgemm128<<<dim3(DIM / 128, ROWS / 128), 256>>>(tok2, DIM, gate_w, 2 * DIM, nullptr, nullptr, nullptr, gatep, DIM, DIM, 0, 0);
    sgemm128<<<dim3(DIM / 128, ROWS / 128), 256>>>(upd, DIM, gate_w + DIM, 2 * DIM, gate_b, tok2, upd, gatep, DIM, DIM, 1, 2);
    // gatep now holds tok3

    // FFN
    norm_film_kernel<<<ROWS, 256>>>(gatep, ffn_norm_w, nullptr, hbuf);
    sgemm128<<<dim3(2 * HIDDEN / 128, ROWS / 128), 256>>>(hbuf, DIM, gu_w, DIM, gu_b, nullptr, nullptr, gu, 2 * HIDDEN, DIM, 0, 0);
    silu_mul_kernel<<<(ROWS * HIDDEN / 4 + 255) / 256, 256>>>(gu, v2);
    sgemm128<<<dim3(DIM / 128, ROWS / 128), 256>>>(v2, HIDDEN, down_w, HIDDEN, down_b, gatep, nullptr, out, DIM, HIDDEN, 0, 0);
}